// round 16
// baseline (speedup 1.0000x reference)
#include <cuda_runtime.h>
#include <cuda_bf16.h>
#include <cstdint>

// NonLocalBlock: B=4, C=64, Ci=32, H=W=64, N=4096
// z = supp + W( softmax_n(theta(supp)^T phi(ref)) @ g(ref) ) + wb
//
//  prep : projections; theta pre-scaled log2(e); slice(0,0) writes zout=supp+wb
//  pass1: colsum[m] partials per n-half AND stores P = 2^f' as e4m3 to g_P8
//         (67 MB total -> L2-resident; written once, read once)
//  norm : g'' = g * 1/colsum * 2^14 as e4m3 (scale dodges e4m3 subnormal floor)
//  pass2: pure FP8 GEMM x1 = P g''^T via mma.m16n8k32.e4m3 (no exp at all);
//         x1 *= 2^-14; symmetric exchange; all-warp W-conv epilogue; RED.F32.
// colsum stays fp32-exact; fp8 errors (~6%/elt) average over ~4096 softmax
// terms into the ~1%-of-z attention path -> ~1e-4 rel err.

#define B_ 4
#define C_ 64
#define CI 32
#define N_ 4096
#define LOG2E 1.4426950408889634f
#define INV2P14 6.103515625e-05f

typedef __nv_bfloat16 bf16;

__device__ __align__(16) bf16 g_theta[B_ * N_ * CI];      // [b][n][ci] (x log2e)
__device__ __align__(16) bf16 g_phi[B_ * N_ * CI];        // [b][m][ci]
__device__ __align__(16) bf16 g_gy[B_ * CI * N_];         // [b][ci][m] raw
__device__ __align__(16) uint8_t g_g8[B_ * CI * N_];      // [b][ci][m] e4m3 g''
__device__ __align__(16) uint8_t g_P8[(size_t)B_ * N_ * N_];  // [b][n][m] e4m3 P
__device__ __align__(16) float g_colpart[2][B_ * N_];     // [half][b][m]

__device__ __forceinline__ uint32_t pack_bf2(float x, float y) {
    __nv_bfloat162 h = __float22bfloat162_rn(make_float2(x, y));
    return *reinterpret_cast<uint32_t*>(&h);
}

__device__ __forceinline__ uint16_t pk8(float lo, float hi) {
    uint16_t r;
    asm("cvt.rn.satfinite.e4m3x2.f32 %0, %1, %2;" : "=h"(r) : "f"(hi), "f"(lo));
    return r;
}

__device__ __forceinline__ float ex2f(float x) {
    float y;
    asm("ex2.approx.ftz.f32 %0, %1;" : "=f"(y) : "f"(x));
    return y;
}

__device__ __forceinline__ uint32_t smem_u32(const void* p) {
    return (uint32_t)__cvta_generic_to_shared(p);
}

__device__ __forceinline__ void ldsm_x4(uint32_t* r, uint32_t addr) {
    asm volatile("ldmatrix.sync.aligned.m8n8.x4.shared.b16 {%0,%1,%2,%3}, [%4];"
        : "=r"(r[0]), "=r"(r[1]), "=r"(r[2]), "=r"(r[3]) : "r"(addr));
}

__device__ __forceinline__ void mma16816(float* c, const uint32_t* a, const uint32_t* b) {
    asm volatile(
        "mma.sync.aligned.m16n8k16.row.col.f32.bf16.bf16.f32 "
        "{%0,%1,%2,%3}, {%4,%5,%6,%7}, {%8,%9}, {%0,%1,%2,%3};\n"
        : "+f"(c[0]), "+f"(c[1]), "+f"(c[2]), "+f"(c[3])
        : "r"(a[0]), "r"(a[1]), "r"(a[2]), "r"(a[3]), "r"(b[0]), "r"(b[1]));
}

__device__ __forceinline__ void mma_e4m3(float* c, const uint32_t* a, const uint32_t* b) {
    asm volatile(
        "mma.sync.aligned.m16n8k32.row.col.f32.e4m3.e4m3.f32 "
        "{%0,%1,%2,%3}, {%4,%5,%6,%7}, {%8,%9}, {%0,%1,%2,%3};\n"
        : "+f"(c[0]), "+f"(c[1]), "+f"(c[2]), "+f"(c[3])
        : "r"(a[0]), "r"(a[1]), "r"(a[2]), "r"(a[3]), "r"(b[0]), "r"(b[1]));
}

__device__ __forceinline__ void cp16(void* dst, const void* src) {
    uint32_t s = (uint32_t)__cvta_generic_to_shared(dst);
    asm volatile("cp.async.cg.shared.global [%0], [%1], 16;\n" :: "r"(s), "l"(src));
}
#define CP_COMMIT asm volatile("cp.async.commit_group;\n")
#define CP_WAIT0  asm volatile("cp.async.wait_group 0;\n")

// ---------------------------------------------------------------------------
// prep: grid (N/256, B, 12), block 256. z = proj*4 + quarter; 8 outputs/thread.
// Slice (proj=0, q=0) also streams zout = supp + wb.
// ---------------------------------------------------------------------------
__global__ __launch_bounds__(256) void prep_kernel(
    const float* __restrict__ supp, const float* __restrict__ ref,
    const float* __restrict__ tw, const float* __restrict__ tb,
    const float* __restrict__ pw, const float* __restrict__ pb,
    const float* __restrict__ gw, const float* __restrict__ gb,
    const float* __restrict__ wb, float* __restrict__ zout) {
    __shared__ float sw[8 * C_];
    __shared__ float sb[8];
    __shared__ float wbs[C_];
    int tid = threadIdx.x;
    int z = blockIdx.z;
    int proj = z >> 2, q = z & 3;
    const float* wsel = (proj == 0) ? tw : (proj == 1) ? pw : gw;
    const float* bsel = (proj == 0) ? tb : (proj == 1) ? pb : gb;
    const float* xsel = (proj == 0) ? supp : ref;
    for (int i = tid; i < 8 * C_; i += 256) sw[i] = wsel[q * 8 * C_ + i];
    if (tid < 8) sb[tid] = bsel[q * 8 + tid];
    if (proj == 0 && q == 0 && tid < C_) wbs[tid] = wb[tid];
    __syncthreads();

    int b = blockIdx.y;
    int n = blockIdx.x * 256 + tid;
    const float* xp = xsel + (size_t)b * C_ * N_ + n;
    float* zp = zout + (size_t)b * C_ * N_ + n;

    float acc[8];
#pragma unroll
    for (int i = 0; i < 8; i++) acc[i] = sb[i];
    if (proj == 0) {
#pragma unroll
        for (int c0 = 0; c0 < C_; c0 += 16) {
            float v[16];
#pragma unroll
            for (int k = 0; k < 16; k++) v[k] = xp[(size_t)(c0 + k) * N_];
            if (q == 0) {
#pragma unroll
                for (int k = 0; k < 16; k++) zp[(size_t)(c0 + k) * N_] = v[k] + wbs[c0 + k];
            }
#pragma unroll
            for (int k = 0; k < 16; k++)
#pragma unroll
                for (int i = 0; i < 8; i++) acc[i] += sw[i * C_ + c0 + k] * v[k];
        }
#pragma unroll
        for (int i = 0; i < 8; i++) acc[i] *= LOG2E;
        uint32_t* dst = (uint32_t*)(g_theta + (size_t)b * N_ * CI) + (size_t)n * 16 + q * 4;
#pragma unroll
        for (int i = 0; i < 4; i++) dst[i] = pack_bf2(acc[2 * i], acc[2 * i + 1]);
        return;
    }
#pragma unroll
    for (int c0 = 0; c0 < C_; c0 += 16) {
        float v[16];
#pragma unroll
        for (int k = 0; k < 16; k++) v[k] = xp[(size_t)(c0 + k) * N_];
#pragma unroll
        for (int k = 0; k < 16; k++)
#pragma unroll
            for (int i = 0; i < 8; i++) acc[i] += sw[i * C_ + c0 + k] * v[k];
    }
    if (proj == 1) {
        uint32_t* dst = (uint32_t*)(g_phi + (size_t)b * N_ * CI) + (size_t)n * 16 + q * 4;
#pragma unroll
        for (int i = 0; i < 4; i++) dst[i] = pack_bf2(acc[2 * i], acc[2 * i + 1]);
    } else {
#pragma unroll
        for (int i = 0; i < 8; i++)
            g_gy[(size_t)b * CI * N_ + (size_t)(q * 8 + i) * N_ + n] = __float2bfloat16(acc[i]);
    }
}

// ---------------------------------------------------------------------------
// norm: g'' = g * 1/(cp0+cp1) * 2^14 as e4m3. grid (8, B), block 256.
// ---------------------------------------------------------------------------
__global__ __launch_bounds__(256) void norm_kernel() {
    int b = blockIdx.y;
    int m = (blockIdx.x * 256 + threadIdx.x) * 2;
    const float* cp0 = g_colpart[0] + (size_t)b * N_;
    const float* cp1 = g_colpart[1] + (size_t)b * N_;
    float2 s0 = *(const float2*)(cp0 + m);
    float2 s1 = *(const float2*)(cp1 + m);
    float ix = 16384.0f / (s0.x + s1.x);
    float iy = 16384.0f / (s0.y + s1.y);
    const bf16* gB = g_gy + (size_t)b * CI * N_ + m;
    uint8_t* g8 = g_g8 + (size_t)b * CI * N_ + m;
#pragma unroll
    for (int ci = 0; ci < CI; ci++) {
        uint32_t u = *(const uint32_t*)(gB + (size_t)ci * N_);
        float2 v = __bfloat1622float2(*(const __nv_bfloat162*)&u);
        *(uint16_t*)(g8 + (size_t)ci * N_) = pk8(v.x * ix, v.y * iy);
    }
}

// ---------------------------------------------------------------------------
// pass1: grid (N/64 m-tiles, B, 2 n-halves), block 256 (8 warps x 16 rows).
// Computes e = 2^f', accumulates partial colsums, stores P = e4m3(e) to g_P8
// via staged smem tile (coalesced 16B global stores).
// ---------------------------------------------------------------------------
__global__ __launch_bounds__(256) void pass1_kernel() {
    __shared__ __align__(16) bf16 At[2][128 * 40];
    __shared__ __align__(16) uint16_t Pst[128 * 40];  // 80B row stride (40 u16)
    __shared__ float cs[64];
    int tid = threadIdx.x;
    int lane = tid & 31, w = tid >> 5;
    int g = lane >> 2, tg = lane & 3;
    int b = blockIdx.y;
    int half = blockIdx.z;
    int m0 = blockIdx.x * 64;
    const bf16* thB = g_theta + (size_t)b * N_ * CI + (size_t)half * 2048 * CI;
    const bf16* phB = g_phi + (size_t)b * N_ * CI;
    uint8_t* Pd = g_P8 + ((size_t)b * N_ + (size_t)half * 2048) * N_;

    uint32_t bfr[8][2][2];
#pragma unroll
    for (int j = 0; j < 8; j++)
#pragma unroll
        for (int kk = 0; kk < 2; kk++) {
            const bf16* p = phB + (size_t)(m0 + j * 8 + g) * CI + kk * 16 + tg * 2;
            bfr[j][kk][0] = *(const uint32_t*)p;
            bfr[j][kk][1] = *(const uint32_t*)(p + 8);
        }
    float part[16];
#pragma unroll
    for (int i = 0; i < 16; i++) part[i] = 0.f;
    if (tid < 64) cs[tid] = 0.f;

    int r8 = lane & 7, q8 = lane >> 3;
    uint32_t aoff = ((w * 16 + (q8 & 1) * 8 + r8) * 40 + (q8 >> 1) * 8) * 2;

    {   // prologue: theta tile 0
        int i0 = tid, i1 = tid + 256;
        cp16(&At[0][(i0 >> 2) * 40 + (i0 & 3) * 8], thB + (size_t)(i0 >> 2) * CI + (i0 & 3) * 8);
        cp16(&At[0][(i1 >> 2) * 40 + (i1 & 3) * 8], thB + (size_t)(i1 >> 2) * CI + (i1 & 3) * 8);
        CP_COMMIT;
    }
    for (int nt = 0; nt < 16; ++nt) {
        CP_WAIT0;
        __syncthreads();
        if (nt + 1 < 16) {
            const bf16* s = thB + (size_t)(nt + 1) * 128 * CI;
            bf16* d = At[(nt + 1) & 1];
            int i0 = tid, i1 = tid + 256;
            cp16(&d[(i0 >> 2) * 40 + (i0 & 3) * 8], s + (size_t)(i0 >> 2) * CI + (i0 & 3) * 8);
            cp16(&d[(i1 >> 2) * 40 + (i1 & 3) * 8], s + (size_t)(i1 >> 2) * CI + (i1 & 3) * 8);
            CP_COMMIT;
        }
        uint32_t a[2][4];
        uint32_t abase = smem_u32(At[nt & 1]) + aoff;
        ldsm_x4(a[0], abase);
        ldsm_x4(a[1], abase + 32);
#pragma unroll
        for (int j = 0; j < 8; j++) {
            float c[4] = {0.f, 0.f, 0.f, 0.f};
            mma16816(c, a[0], bfr[j][0]);
            mma16816(c, a[1], bfr[j][1]);
            float e0 = ex2f(c[0]), e1 = ex2f(c[1]);
            float e2 = ex2f(c[2]), e3 = ex2f(c[3]);
            part[j * 2] += e0 + e2;
            part[j * 2 + 1] += e1 + e3;
            Pst[(w * 16 + g) * 40 + j * 4 + tg] = pk8(e0, e1);
            Pst[(w * 16 + g + 8) * 40 + j * 4 + tg] = pk8(e2, e3);
        }
        __syncthreads();
        // staged tile -> global (128 rows x 64 B = 512 x 16B chunks)
        {
            uint8_t* dst0 = Pd + (size_t)(nt * 128) * N_ + m0;
#pragma unroll
            for (int k = 0; k < 2; k++) {
                int idx = tid + k * 256;
                int r = idx >> 2, q = idx & 3;
                *(uint4*)(dst0 + (size_t)r * N_ + q * 16) =
                    *(const uint4*)((const char*)Pst + r * 80 + q * 16);
            }
        }
    }
#pragma unroll
    for (int off = 4; off <= 16; off <<= 1)
#pragma unroll
        for (int i = 0; i < 16; i++) part[i] += __shfl_xor_sync(0xffffffffu, part[i], off);
    __syncthreads();
    if (g == 0) {
#pragma unroll
        for (int j = 0; j < 8; j++) {
            atomicAdd(&cs[j * 8 + tg * 2], part[j * 2]);
            atomicAdd(&cs[j * 8 + tg * 2 + 1], part[j * 2 + 1]);
        }
    }
    __syncthreads();
    if (tid < 64) g_colpart[half][(size_t)b * N_ + m0 + tid] = cs[tid];
}

// ---------------------------------------------------------------------------
// pass2: pure FP8 GEMM. grid (N/64 n-tiles, B, 2 m-halves), block 256.
// wq=w&3 (16 rows), mh=w>>2 (32-wide k-slice of each 64-wide m tile).
// x1 = P g''^T via mma.m16n8k32.e4m3; x1 *= 2^-14; symmetric exchange;
// all-8-warp split W-conv epilogue; RED.F32 into zout.
// ---------------------------------------------------------------------------
__global__ __launch_bounds__(256) void pass2_kernel(
    const float* __restrict__ ww, float* __restrict__ zout) {
    __shared__ __align__(16) char sm[22528];
    uint8_t* Pt = (uint8_t*)sm;            // 2 x 64*80 = 10240 B
    uint8_t* Gt = (uint8_t*)(sm + 10240);  // 2 x 32*80 =  5120 B
    bf16* Ws = (bf16*)(sm + 17408);        // 64*40 bf16 = 5120 B
    float* xr = (float*)sm;                // alias after mainloop: 17408 B
    int tid = threadIdx.x;
    int lane = tid & 31, w = tid >> 5;
    int wq = w & 3, mh = w >> 2;
    int g = lane >> 2, tg = lane & 3;
    int b = blockIdx.y;
    int hb = blockIdx.z;
    int n0 = blockIdx.x * 64;
    const uint8_t* PB = g_P8 + (size_t)b * N_ * N_ + (size_t)hb * 2048;
    const uint8_t* g8B = g_g8 + (size_t)b * CI * N_ + hb * 2048;

    for (int i = tid; i < C_ * CI; i += 256)
        Ws[(i >> 5) * 40 + (i & 31)] = __float2bfloat16(ww[i]);

    float x1[4][4];
#pragma unroll
    for (int i = 0; i < 4; i++)
#pragma unroll
        for (int k = 0; k < 4; k++) x1[i][k] = 0.f;

    auto issue = [&](int mt, int bufi) {
        int mb = mt * 64;
        uint8_t* PtB = Pt + bufi * (64 * 80);
        uint8_t* GtB = Gt + bufi * (32 * 80);
        {   // P: 64 rows x 64 B = 256 chunks, 1/thread
            int r = tid >> 2, q = tid & 3;
            cp16(PtB + r * 80 + q * 16, PB + (size_t)(n0 + r) * N_ + mb + q * 16);
        }
        if (tid < 128) {  // g'': 32 rows x 64 B = 128 chunks
            int r = tid >> 2, q = tid & 3;
            cp16(GtB + r * 80 + q * 16, g8B + (size_t)r * N_ + mb + q * 16);
        }
    };

    issue(0, 0);
    CP_COMMIT;
    for (int mt = 0; mt < 32; ++mt) {
        CP_WAIT0;
        __syncthreads();
        if (mt + 1 < 32) { issue(mt + 1, (mt + 1) & 1); CP_COMMIT; }
        int bufi = mt & 1;
        const uint8_t* PtB = Pt + bufi * (64 * 80) + (wq * 16) * 80;
        const uint8_t* GtB = Gt + bufi * (32 * 80);
        uint32_t a[4];
        a[0] = *(const uint32_t*)(PtB + g * 80 + mh * 32 + tg * 4);
        a[1] = *(const uint32_t*)(PtB + (g + 8) * 80 + mh * 32 + tg * 4);
        a[2] = *(const uint32_t*)(PtB + g * 80 + mh * 32 + tg * 4 + 16);
        a[3] = *(const uint32_t*)(PtB + (g + 8) * 80 + mh * 32 + tg * 4 + 16);
#pragma unroll
        for (int cc = 0; cc < 4; cc++) {
            uint32_t bg[2];
            const uint8_t* p = GtB + (cc * 8 + g) * 80 + mh * 32 + tg * 4;
            bg[0] = *(const uint32_t*)p;
            bg[1] = *(const uint32_t*)(p + 16);
            mma_e4m3(x1[cc], a, bg);
        }
    }
#pragma unroll
    for (int cc = 0; cc < 4; cc++)
#pragma unroll
        for (int k = 0; k < 4; k++) x1[cc][k] *= INV2P14;

    // symmetric mh exchange: both halves write, both read the other, both sum.
    __syncthreads();
    {
        float* dst = xr + (mh * 128 + wq * 32 + lane) * 17;
#pragma unroll
        for (int cc = 0; cc < 4; cc++)
#pragma unroll
            for (int k = 0; k < 4; k++) dst[cc * 4 + k] = x1[cc][k];
    }
    __syncthreads();
    {
        const float* src = xr + ((1 - mh) * 128 + wq * 32 + lane) * 17;
#pragma unroll
        for (int cc = 0; cc < 4; cc++)
#pragma unroll
            for (int k = 0; k < 4; k++) x1[cc][k] += src[cc * 4 + k];
    }

    // split W-conv epilogue: warp set mh covers c-columns mh*32..mh*32+31.
    uint32_t ax[2][4];
#pragma unroll
    for (int cc = 0; cc < 4; cc++) {
        int kt = cc >> 1;
        int o = (cc & 1) ? 2 : 0;
        ax[kt][o] = pack_bf2(x1[cc][0], x1[cc][1]);
        ax[kt][o + 1] = pack_bf2(x1[cc][2], x1[cc][3]);
    }
#pragma unroll
    for (int i = 0; i < 4; i++) {
        int cc2 = mh * 4 + i;
        float zc[4] = {0.f, 0.f, 0.f, 0.f};
#pragma unroll
        for (int kk = 0; kk < 2; kk++) {
            uint32_t bw[2];
            const bf16* p = Ws + (cc2 * 8 + g) * 40 + kk * 16 + tg * 2;
            bw[0] = *(const uint32_t*)p;
            bw[1] = *(const uint32_t*)(p + 8);
            mma16816(zc, ax[kk], bw);
        }
        int c = cc2 * 8 + tg * 2;
        int n = n0 + wq * 16 + g;
        size_t base = ((size_t)b * C_ + c) * N_ + n;
        atomicAdd(&zout[base], zc[0]);
        atomicAdd(&zout[base + N_], zc[1]);
        atomicAdd(&zout[base + 8], zc[2]);
        atomicAdd(&zout[base + N_ + 8], zc[3]);
    }
}

extern "C" void kernel_launch(void* const* d_in, const int* in_sizes, int n_in,
                              void* d_out, int out_size) {
    const float* supp = (const float*)d_in[0];
    const float* ref = (const float*)d_in[1];
    const float* tw = (const float*)d_in[2];
    const float* tb = (const float*)d_in[3];
    const float* pw = (const float*)d_in[4];
    const float* pb = (const float*)d_in[5];
    const float* gw = (const float*)d_in[6];
    const float* gb = (const float*)d_in[7];
    const float* ww = (const float*)d_in[8];
    const float* wb = (const float*)d_in[9];
    float* z = (float*)d_out;

    prep_kernel<<<dim3(N_ / 256, B_, 12), 256>>>(supp, ref, tw, tb, pw, pb, gw, gb, wb, z);
    pass1_kernel<<<dim3(N_ / 64, B_, 2), 256>>>();
    norm_kernel<<<dim3(8, B_), 256>>>();
    pass2_kernel<<<dim3(N_ / 64, B_, 2), 256>>>(ww, z);
}

// round 17
// speedup vs baseline: 1.1875x; 1.1875x over previous
#include <cuda_runtime.h>
#include <cuda_bf16.h>
#include <cstdint>

// NonLocalBlock: B=4, C=64, Ci=32, H=W=64, N=4096
// z = supp + W( softmax_n(theta(supp)^T phi(ref)) @ g(ref) ) + wb
//
//  prep : projections; theta (x log2e) and phi stored PRE-TILED+PADDED in the
//         exact smem tile layout; slice(0,0) streams zout = supp + wb
//  pass1: partial colsum[m] = sum_n 2^f' per n-half; theta tiles arrive via
//         ONE cp.async.bulk per iteration (mbarrier complete_tx)
//  norm : g' = g * 1/colsum, stored tiled [b][mt][32][72]
//  pass2: recompute S on an m-half; P = 2^f'; x1 = P g'^T; phi+g tiles via
//         TWO cp.async.bulk per iteration; symmetric exchange; all-warp
//         split W-conv epilogue; RED.F32 into zout.
// Rationale: previous mainloops issued 512 cp.async.cg (LDGSTS rt=8/SMSP)
// per block-iter = ~1024 cyc of pure issue serialization; bulk removes it.

#define B_ 4
#define C_ 64
#define CI 32
#define N_ 4096
#define LOG2E 1.4426950408889634f

typedef __nv_bfloat16 bf16;

__device__ __align__(16) bf16 th_t[B_ * 32 * 128 * 40];  // theta tiled [b][nt][128][40]
__device__ __align__(16) bf16 ph_t[B_ * 64 * 64 * 40];   // phi   tiled [b][mt][64][40]
__device__ __align__(16) bf16 gt_t[B_ * 64 * 32 * 72];   // g'    tiled [b][mt][32][72]
__device__ __align__(16) bf16 g_gy[B_ * CI * N_];        // raw g [b][ci][m]
__device__ __align__(16) float g_colpart[2][B_ * N_];    // [half][b][m]

__device__ __forceinline__ uint32_t pack_bf2(float x, float y) {
    __nv_bfloat162 h = __float22bfloat162_rn(make_float2(x, y));
    return *reinterpret_cast<uint32_t*>(&h);
}

__device__ __forceinline__ float ex2f(float x) {
    float y;
    asm("ex2.approx.ftz.f32 %0, %1;" : "=f"(y) : "f"(x));
    return y;
}

__device__ __forceinline__ uint32_t smem_u32(const void* p) {
    return (uint32_t)__cvta_generic_to_shared(p);
}

__device__ __forceinline__ void ldsm_x4(uint32_t* r, uint32_t addr) {
    asm volatile("ldmatrix.sync.aligned.m8n8.x4.shared.b16 {%0,%1,%2,%3}, [%4];"
        : "=r"(r[0]), "=r"(r[1]), "=r"(r[2]), "=r"(r[3]) : "r"(addr));
}

__device__ __forceinline__ void mma16816(float* c, const uint32_t* a, const uint32_t* b) {
    asm volatile(
        "mma.sync.aligned.m16n8k16.row.col.f32.bf16.bf16.f32 "
        "{%0,%1,%2,%3}, {%4,%5,%6,%7}, {%8,%9}, {%0,%1,%2,%3};\n"
        : "+f"(c[0]), "+f"(c[1]), "+f"(c[2]), "+f"(c[3])
        : "r"(a[0]), "r"(a[1]), "r"(a[2]), "r"(a[3]), "r"(b[0]), "r"(b[1]));
}

__device__ __forceinline__ void mbar_init(uint32_t mbar, uint32_t cnt) {
    asm volatile("mbarrier.init.shared.b64 [%0], %1;" :: "r"(mbar), "r"(cnt) : "memory");
}
__device__ __forceinline__ void mbar_expect(uint32_t mbar, uint32_t bytes) {
    asm volatile("mbarrier.arrive.expect_tx.shared.b64 _, [%0], %1;"
        :: "r"(mbar), "r"(bytes) : "memory");
}
__device__ __forceinline__ void bulk_g2s(uint32_t dst, const void* src, uint32_t bytes,
                                         uint32_t mbar) {
    asm volatile(
        "cp.async.bulk.shared::cluster.global.mbarrier::complete_tx::bytes "
        "[%0], [%1], %2, [%3];"
        :: "r"(dst), "l"(src), "r"(bytes), "r"(mbar) : "memory");
}
__device__ __forceinline__ void mbar_wait(uint32_t mbar, uint32_t parity) {
    asm volatile(
        "{\n\t.reg .pred P;\n\t"
        "W%=:\n\t"
        "mbarrier.try_wait.parity.acquire.cta.shared::cta.b64 P, [%0], %1, 0x989680;\n\t"
        "@P bra D%=;\n\t"
        "bra W%=;\n\t"
        "D%=:\n\t}"
        :: "r"(mbar), "r"(parity) : "memory");
}

// ---------------------------------------------------------------------------
// prep: grid (N/256, B, 12), block 256. z = proj*4 + quarter; 8 outputs/thread.
// theta/phi written in padded tiled layouts. Slice (0,0) streams zout=supp+wb.
// ---------------------------------------------------------------------------
__global__ __launch_bounds__(256) void prep_kernel(
    const float* __restrict__ supp, const float* __restrict__ ref,
    const float* __restrict__ tw, const float* __restrict__ tb,
    const float* __restrict__ pw, const float* __restrict__ pb,
    const float* __restrict__ gw, const float* __restrict__ gb,
    const float* __restrict__ wb, float* __restrict__ zout) {
    __shared__ float sw[8 * C_];
    __shared__ float sb[8];
    __shared__ float wbs[C_];
    int tid = threadIdx.x;
    int z = blockIdx.z;
    int proj = z >> 2, q = z & 3;
    const float* wsel = (proj == 0) ? tw : (proj == 1) ? pw : gw;
    const float* bsel = (proj == 0) ? tb : (proj == 1) ? pb : gb;
    const float* xsel = (proj == 0) ? supp : ref;
    for (int i = tid; i < 8 * C_; i += 256) sw[i] = wsel[q * 8 * C_ + i];
    if (tid < 8) sb[tid] = bsel[q * 8 + tid];
    if (proj == 0 && q == 0 && tid < C_) wbs[tid] = wb[tid];
    __syncthreads();

    int b = blockIdx.y;
    int n = blockIdx.x * 256 + tid;
    const float* xp = xsel + (size_t)b * C_ * N_ + n;
    float* zp = zout + (size_t)b * C_ * N_ + n;

    float acc[8];
#pragma unroll
    for (int i = 0; i < 8; i++) acc[i] = sb[i];
    if (proj == 0) {
#pragma unroll
        for (int c0 = 0; c0 < C_; c0 += 16) {
            float v[16];
#pragma unroll
            for (int k = 0; k < 16; k++) v[k] = xp[(size_t)(c0 + k) * N_];
            if (q == 0) {
#pragma unroll
                for (int k = 0; k < 16; k++) zp[(size_t)(c0 + k) * N_] = v[k] + wbs[c0 + k];
            }
#pragma unroll
            for (int k = 0; k < 16; k++)
#pragma unroll
                for (int i = 0; i < 8; i++) acc[i] += sw[i * C_ + c0 + k] * v[k];
        }
#pragma unroll
        for (int i = 0; i < 8; i++) acc[i] *= LOG2E;
        int nt = n >> 7, r = n & 127;
        uint32_t* dst = (uint32_t*)th_t + ((size_t)(b * 32 + nt) * 128 + r) * 20 + q * 4;
#pragma unroll
        for (int i = 0; i < 4; i++) dst[i] = pack_bf2(acc[2 * i], acc[2 * i + 1]);
        return;
    }
#pragma unroll
    for (int c0 = 0; c0 < C_; c0 += 16) {
        float v[16];
#pragma unroll
        for (int k = 0; k < 16; k++) v[k] = xp[(size_t)(c0 + k) * N_];
#pragma unroll
        for (int k = 0; k < 16; k++)
#pragma unroll
            for (int i = 0; i < 8; i++) acc[i] += sw[i * C_ + c0 + k] * v[k];
    }
    if (proj == 1) {
        int nt = n >> 6, r = n & 63;
        uint32_t* dst = (uint32_t*)ph_t + ((size_t)(b * 64 + nt) * 64 + r) * 20 + q * 4;
#pragma unroll
        for (int i = 0; i < 4; i++) dst[i] = pack_bf2(acc[2 * i], acc[2 * i + 1]);
    } else {
#pragma unroll
        for (int i = 0; i < 8; i++)
            g_gy[(size_t)b * CI * N_ + (size_t)(q * 8 + i) * N_ + n] = __float2bfloat16(acc[i]);
    }
}

// ---------------------------------------------------------------------------
// norm: g' = g * 1/(cp0+cp1) written tiled [b][mt][32][72]. grid (8, B).
// ---------------------------------------------------------------------------
__global__ __launch_bounds__(256) void norm_kernel() {
    int b = blockIdx.y;
    int m = (blockIdx.x * 256 + threadIdx.x) * 2;
    const float* cp0 = g_colpart[0] + (size_t)b * N_;
    const float* cp1 = g_colpart[1] + (size_t)b * N_;
    float2 s0 = *(const float2*)(cp0 + m);
    float2 s1 = *(const float2*)(cp1 + m);
    float ix = 1.0f / (s0.x + s1.x);
    float iy = 1.0f / (s0.y + s1.y);
    const bf16* gB = g_gy + (size_t)b * CI * N_ + m;
    int mt = m >> 6, cm = m & 63;
    uint32_t* gt = (uint32_t*)gt_t + ((size_t)(b * 64 + mt) * 32) * 36 + (cm >> 1);
#pragma unroll
    for (int ci = 0; ci < CI; ci++) {
        uint32_t u = *(const uint32_t*)(gB + (size_t)ci * N_);
        float2 v = __bfloat1622float2(*(const __nv_bfloat162*)&u);
        gt[(size_t)ci * 36] = pack_bf2(v.x * ix, v.y * iy);
    }
}

// ---------------------------------------------------------------------------
// pass1: grid (N/64 m-tiles, B, 2 n-halves), block 256 (8 warps x 16 rows).
// Theta tile (10240 B) arrives via one cp.async.bulk per iteration.
// ---------------------------------------------------------------------------
__global__ __launch_bounds__(256) void pass1_kernel() {
    __shared__ __align__(16) bf16 At[2][128 * 40];
    __shared__ __align__(8) unsigned long long mbar[2];
    __shared__ float cs[64];
    int tid = threadIdx.x;
    int lane = tid & 31, w = tid >> 5;
    int g = lane >> 2, tg = lane & 3;
    int b = blockIdx.y;
    int half = blockIdx.z;
    int m0 = blockIdx.x * 64;
    const bf16* thT = th_t + (size_t)(b * 32 + half * 16) * (128 * 40);
    const bf16* phT = ph_t + (size_t)(b * 64 + (m0 >> 6)) * (64 * 40);

    uint32_t mb0 = smem_u32(&mbar[0]), mb1 = smem_u32(&mbar[1]);
    if (tid == 0) { mbar_init(mb0, 1); mbar_init(mb1, 1); }
    __syncthreads();

    uint32_t bfr[8][2][2];
#pragma unroll
    for (int j = 0; j < 8; j++)
#pragma unroll
        for (int kk = 0; kk < 2; kk++) {
            const bf16* p = phT + (size_t)(j * 8 + g) * 40 + kk * 16 + tg * 2;
            bfr[j][kk][0] = *(const uint32_t*)p;
            bfr[j][kk][1] = *(const uint32_t*)(p + 8);
        }
    float part[16];
#pragma unroll
    for (int i = 0; i < 16; i++) part[i] = 0.f;
    if (tid < 64) cs[tid] = 0.f;

    int r8 = lane & 7, q8 = lane >> 3;
    uint32_t aoff = ((w * 16 + (q8 & 1) * 8 + r8) * 40 + (q8 >> 1) * 8) * 2;

    if (tid == 0) {
        mbar_expect(mb0, 10240);
        bulk_g2s(smem_u32(At[0]), thT, 10240, mb0);
    }
    for (int nt = 0; nt < 16; ++nt) {
        __syncthreads();
        if (tid == 0 && nt + 1 < 16) {
            uint32_t mb = (nt + 1) & 1 ? mb1 : mb0;
            mbar_expect(mb, 10240);
            bulk_g2s(smem_u32(At[(nt + 1) & 1]), thT + (size_t)(nt + 1) * (128 * 40), 10240, mb);
        }
        mbar_wait((nt & 1) ? mb1 : mb0, (nt >> 1) & 1);
        uint32_t a[2][4];
        uint32_t abase = smem_u32(At[nt & 1]) + aoff;
        ldsm_x4(a[0], abase);
        ldsm_x4(a[1], abase + 32);
#pragma unroll
        for (int j = 0; j < 8; j++) {
            float c[4] = {0.f, 0.f, 0.f, 0.f};
            mma16816(c, a[0], bfr[j][0]);
            mma16816(c, a[1], bfr[j][1]);
            part[j * 2] += ex2f(c[0]) + ex2f(c[2]);
            part[j * 2 + 1] += ex2f(c[1]) + ex2f(c[3]);
        }
    }
#pragma unroll
    for (int off = 4; off <= 16; off <<= 1)
#pragma unroll
        for (int i = 0; i < 16; i++) part[i] += __shfl_xor_sync(0xffffffffu, part[i], off);
    __syncthreads();
    if (g == 0) {
#pragma unroll
        for (int j = 0; j < 8; j++) {
            atomicAdd(&cs[j * 8 + tg * 2], part[j * 2]);
            atomicAdd(&cs[j * 8 + tg * 2 + 1], part[j * 2 + 1]);
        }
    }
    __syncthreads();
    if (tid < 64) g_colpart[half][(size_t)b * N_ + m0 + tid] = cs[tid];
}

// ---------------------------------------------------------------------------
// pass2: grid (N/64 n-tiles, B, 2 m-halves), block 256 (8 warps), 32 iters.
// wq=w&3 (16 rows), mh=w>>2 (32-wide m-slice). Phi (5120 B) + g' (4608 B)
// tiles arrive via two cp.async.bulk per iteration. Symmetric exchange;
// all-8-warp split W-conv epilogue; RED.F32 into zout.
// ---------------------------------------------------------------------------
__global__ __launch_bounds__(256) void pass2_kernel(
    const float* __restrict__ ww, float* __restrict__ zout) {
    __shared__ __align__(16) char sm[24576];
    bf16* Ph = (bf16*)sm;            // 2 x 64*40 bf16 = 10240 B
    bf16* Gt = (bf16*)(sm + 10240);  // 2 x 32*72 bf16 =  9216 B
    bf16* Ws = (bf16*)(sm + 19456);  // 64*40 bf16    =  5120 B
    float* xr = (float*)sm;          // alias after mainloop: 17408 B
    __shared__ __align__(8) unsigned long long mbar[2];
    int tid = threadIdx.x;
    int lane = tid & 31, w = tid >> 5;
    int wq = w & 3, mh = w >> 2;
    int g = lane >> 2, tg = lane & 3;
    int b = blockIdx.y;
    int hb = blockIdx.z;
    int n0 = blockIdx.x * 64;
    const bf16* phT = ph_t + (size_t)(b * 64 + hb * 32) * (64 * 40);
    const bf16* gtT = gt_t + (size_t)(b * 64 + hb * 32) * (32 * 72);

    uint32_t mb0 = smem_u32(&mbar[0]), mb1 = smem_u32(&mbar[1]);
    if (tid == 0) { mbar_init(mb0, 1); mbar_init(mb1, 1); }

    for (int i = tid; i < C_ * CI; i += 256)
        Ws[(i >> 5) * 40 + (i & 31)] = __float2bfloat16(ww[i]);

    // A fragments (theta rows n0 + wq*16) from tiled theta (row stride 40)
    uint32_t a[2][4];
    {
        const bf16* Ar = th_t + ((size_t)(b * 32 + (n0 >> 7)) * 128 + (n0 & 127) + wq * 16) * 40;
#pragma unroll
        for (int kk = 0; kk < 2; kk++) {
            a[kk][0] = *(const uint32_t*)(Ar + (size_t)g * 40 + kk * 16 + tg * 2);
            a[kk][1] = *(const uint32_t*)(Ar + (size_t)(g + 8) * 40 + kk * 16 + tg * 2);
            a[kk][2] = *(const uint32_t*)(Ar + (size_t)g * 40 + kk * 16 + tg * 2 + 8);
            a[kk][3] = *(const uint32_t*)(Ar + (size_t)(g + 8) * 40 + kk * 16 + tg * 2 + 8);
        }
    }
    float x1[4][4];
#pragma unroll
    for (int i = 0; i < 4; i++)
#pragma unroll
        for (int k = 0; k < 4; k++) x1[i][k] = 0.f;

    int r8 = lane & 7, q8 = lane >> 3;
    uint32_t bpoff = (uint32_t)(((mh * 32 + r8) * 40 + q8 * 8) * 2);
    uint32_t bgoff = (uint32_t)((r8 * 72 + mh * 32 + q8 * 8) * 2);

    __syncthreads();  // mbar init + Ws visible
    if (tid == 0) {
        mbar_expect(mb0, 9728);
        bulk_g2s(smem_u32(Ph), phT, 5120, mb0);
        bulk_g2s(smem_u32(Gt), gtT, 4608, mb0);
    }
    for (int mt = 0; mt < 32; ++mt) {
        __syncthreads();
        if (tid == 0 && mt + 1 < 32) {
            int bi = (mt + 1) & 1;
            uint32_t mb = bi ? mb1 : mb0;
            mbar_expect(mb, 9728);
            bulk_g2s(smem_u32(Ph + bi * (64 * 40)), phT + (size_t)(mt + 1) * (64 * 40), 5120, mb);
            bulk_g2s(smem_u32(Gt + bi * (32 * 72)), gtT + (size_t)(mt + 1) * (32 * 72), 4608, mb);
        }
        mbar_wait((mt & 1) ? mb1 : mb0, (mt >> 1) & 1);
        int bufi = mt & 1;
        uint32_t phbase = smem_u32(Ph + bufi * (64 * 40)) + bpoff;
        uint32_t ap[2][4];
#pragma unroll
        for (int j = 0; j < 4; j++) {
            uint32_t bp[4];  // {kk0 klo, kk0 khi, kk1 klo, kk1 khi}
            ldsm_x4(bp, phbase + j * (8 * 40 * 2));
            float c[4] = {0.f, 0.f, 0.f, 0.f};
            mma16816(c, a[0], bp);
            mma16816(c, a[1], bp + 2);
            int kt = j >> 1;
            int o = (j & 1) ? 2 : 0;
            ap[kt][o] = pack_bf2(ex2f(c[0]), ex2f(c[1]));
            ap[kt][o + 1] = pack_bf2(ex2f(c[2]), ex2f(c[3]));
        }
        uint32_t gtbase = smem_u32(Gt + bufi * (32 * 72)) + bgoff;
#pragma unroll
        for (int cc = 0; cc < 4; cc++) {
            uint32_t bg[4];  // {kt0 klo, kt0 khi, kt1 klo, kt1 khi}
            ldsm_x4(bg, gtbase + cc * (8 * 72 * 2));
            mma16816(x1[cc], ap[0], bg);
            mma16816(x1[cc], ap[1], bg + 2);
        }
    }

    // symmetric mh exchange: both halves write, both read the other, both sum.
    __syncthreads();
    {
        float* dst = xr + (mh * 128 + wq * 32 + lane) * 17;
#pragma unroll
        for (int cc = 0; cc < 4; cc++)
#pragma unroll
            for (int k = 0; k < 4; k++) dst[cc * 4 + k] = x1[cc][k];
    }
    __syncthreads();
    {
        const float* src = xr + ((1 - mh) * 128 + wq * 32 + lane) * 17;
#pragma unroll
        for (int cc = 0; cc < 4; cc++)
#pragma unroll
            for (int k = 0; k < 4; k++) x1[cc][k] += src[cc * 4 + k];
    }

    // split W-conv epilogue: warp set mh covers c-columns mh*32..mh*32+31.
    uint32_t ax[2][4];
#pragma unroll
    for (int cc = 0; cc < 4; cc++) {
        int kt = cc >> 1;
        int o = (cc & 1) ? 2 : 0;
        ax[kt][o] = pack_bf2(x1[cc][0], x1[cc][1]);
        ax[kt][o + 1] = pack_bf2(x1[cc][2], x1[cc][3]);
    }
#pragma unroll
    for (int i = 0; i < 4; i++) {
        int cc2 = mh * 4 + i;
        float zc[4] = {0.f, 0.f, 0.f, 0.f};
#pragma unroll
        for (int kk = 0; kk < 2; kk++) {
            uint32_t bw[2];
            const bf16* p = Ws + (cc2 * 8 + g) * 40 + kk * 16 + tg * 2;
            bw[0] = *(const uint32_t*)p;
            bw[1] = *(const uint32_t*)(p + 8);
            mma16816(zc, ax[kk], bw);
        }
        int c = cc2 * 8 + tg * 2;
        int n = n0 + wq * 16 + g;
        size_t base = ((size_t)b * C_ + c) * N_ + n;
        atomicAdd(&zout[base], zc[0]);
        atomicAdd(&zout[base + N_], zc[1]);
        atomicAdd(&zout[base + 8], zc[2]);
        atomicAdd(&zout[base + N_ + 8], zc[3]);
    }
}

extern "C" void kernel_launch(void* const* d_in, const int* in_sizes, int n_in,
                              void* d_out, int out_size) {
    const float* supp = (const float*)d_in[0];
    const float* ref = (const float*)d_in[1];
    const float* tw = (const float*)d_in[2];
    const float* tb = (const float*)d_in[3];
    const float* pw = (const float*)d_in[4];
    const float* pb = (const float*)d_in[5];
    const float* gw = (const float*)d_in[6];
    const float* gb = (const float*)d_in[7];
    const float* ww = (const float*)d_in[8];
    const float* wb = (const float*)d_in[9];
    float* z = (float*)d_out;

    prep_kernel<<<dim3(N_ / 256, B_, 12), 256>>>(supp, ref, tw, tb, pw, pb, gw, gb, wb, z);
    pass1_kernel<<<dim3(N_ / 64, B_, 2), 256>>>();
    norm_kernel<<<dim3(8, B_), 256>>>();
    pass2_kernel<<<dim3(N_ / 64, B_, 2), 256>>>(ww, z);
}